// round 15
// baseline (speedup 1.0000x reference)
#include <cuda_runtime.h>
#include <cstdint>

#define NN       8192
#define THREADS  512                 // 16 warps per block, 128-reg budget
#define SCAN_T   512
#define GBLOCKS  128                 // 128*16 warps * 2 rows = 4096 = D

__device__ float g_zero = 0.0f;

// ---------------------------------------------------------------------------
// TWO rows per WARP (r and r+D/2), interleaved chunk-by-chunk. 16 chunks of
// 512 elements per row; lane l owns float4s {0,32,64,96}+l (coalesced
// LDG.128 = 512B contiguous). Depth-1 prefetch of BOTH rows' next chunk
// (4KB in flight per warp). cb loaded once per chunk, shared by both rows.
// Eight interleaved warp scans; zero block barriers in the main loop.
// ---------------------------------------------------------------------------
__global__ void __launch_bounds__(THREADS, 1)
row_w1_kernel(const float* __restrict__ x, const float* __restrict__ bary,
              float* __restrict__ out, int D)
{
    __shared__ __align__(16) float cb[NN];
    __shared__ float ws[SCAN_T / 32];

    const int t    = threadIdx.x;
    const int lane = t & 31;
    const int wid  = t >> 5;

    // ---- build cb in smem: 512 threads, 16 elements each ----
    {
        const float4* bp = reinterpret_cast<const float4*>(bary) + t * 4;
        float4 q0 = bp[0], q1 = bp[1], q2 = bp[2], q3 = bp[3];

        float p00 = q0.x;
        float p01 = p00 + q0.y;
        float p02 = p01 + q0.z;
        float p03 = p02 + q0.w;
        float p04 = p03 + q1.x;
        float p05 = p04 + q1.y;
        float p06 = p05 + q1.z;
        float p07 = p06 + q1.w;
        float p08 = p07 + q2.x;
        float p09 = p08 + q2.y;
        float p10 = p09 + q2.z;
        float p11 = p10 + q2.w;
        float p12 = p11 + q3.x;
        float p13 = p12 + q3.y;
        float p14 = p13 + q3.z;
        float p15 = p14 + q3.w;

        float s = p15;
        #pragma unroll
        for (int o = 1; o < 32; o <<= 1) {
            float y = __shfl_up_sync(0xFFFFFFFFu, s, o);
            if (lane >= o) s += y;
        }
        if (lane == 31) ws[wid] = s;
        __syncthreads();
        float w = (lane < SCAN_T / 32) ? ws[lane] : 0.0f;
        #pragma unroll
        for (int o = 1; o < SCAN_T / 32; o <<= 1) {
            float y = __shfl_up_sync(0xFFFFFFFFu, w, o);
            if (lane >= o) w += y;
        }
        float woff = (wid > 0) ? __shfl_sync(0xFFFFFFFFu, w, wid - 1) : 0.0f;
        float off = woff + (s - p15);

        float* c = cb + t * 16;
        c[0]  = off + p00;  c[1]  = off + p01;  c[2]  = off + p02;  c[3]  = off + p03;
        c[4]  = off + p04;  c[5]  = off + p05;  c[6]  = off + p06;  c[7]  = off + p07;
        c[8]  = off + p08;  c[9]  = off + p09;  c[10] = off + p10;  c[11] = off + p11;
        c[12] = off + p12;  c[13] = off + p13;  c[14] = off + p14;  c[15] = off + p15;

        // block 0 also writes bary into out[1..N]
        if (blockIdx.x == 0) {
            float* o = out + 1 + t * 16;
            o[0]=q0.x;  o[1]=q0.y;  o[2]=q0.z;  o[3]=q0.w;
            o[4]=q1.x;  o[5]=q1.y;  o[6]=q1.z;  o[7]=q1.w;
            o[8]=q2.x;  o[9]=q2.y;  o[10]=q2.z; o[11]=q2.w;
            o[12]=q3.x; o[13]=q3.y; o[14]=q3.z; o[15]=q3.w;
        }
    }
    __syncthreads();

    // ---- main: two rows per warp, zero block barriers ----
    const int half = D >> 1;                     // 2048
    const int rX   = blockIdx.x * (THREADS / 32) + wid;   // 0..2047
    const int rY   = rX + half;

    const float4* pX = reinterpret_cast<const float4*>(x + (size_t)rX * NN) + lane;
    const float4* pY = reinterpret_cast<const float4*>(x + (size_t)rY * NN) + lane;
    const float4* cc = reinterpret_cast<const float4*>(cb) + lane;

    // prologue: chunk 0 of both rows
    float4 vX0 = pX[0], vX1 = pX[32], vX2 = pX[64], vX3 = pX[96];
    float4 vY0 = pY[0], vY1 = pY[32], vY2 = pY[64], vY3 = pY[96];
    float4 nX0, nX1, nX2, nX3, nY0, nY1, nY2, nY3;

    float offX = 0.0f, offY = 0.0f;
    float acc0 = 0.0f, acc1 = 0.0f, acc2 = 0.0f, acc3 = 0.0f;

    #pragma unroll 1
    for (int c = 0; c < 16; ++c) {
        // depth-1 prefetch of next chunk for both rows
        if (c < 15) {
            const float4* qX = pX + 128;
            const float4* qY = pY + 128;
            nX0 = qX[0]; nX1 = qX[32]; nX2 = qX[64]; nX3 = qX[96];
            nY0 = qY[0]; nY1 = qY[32]; nY2 = qY[64]; nY3 = qY[96];
        }

        // in-lane inclusive scans (8 independent chains)
        float a0 = vX0.x, a1 = a0 + vX0.y, a2 = a1 + vX0.z, a3 = a2 + vX0.w;
        float b0 = vX1.x, b1 = b0 + vX1.y, b2 = b1 + vX1.z, b3 = b2 + vX1.w;
        float d0 = vX2.x, d1 = d0 + vX2.y, d2 = d1 + vX2.z, d3 = d2 + vX2.w;
        float e0 = vX3.x, e1 = e0 + vX3.y, e2 = e1 + vX3.z, e3 = e2 + vX3.w;
        float f0 = vY0.x, f1 = f0 + vY0.y, f2 = f1 + vY0.z, f3 = f2 + vY0.w;
        float g0 = vY1.x, g1 = g0 + vY1.y, g2 = g1 + vY1.z, g3 = g2 + vY1.w;
        float h0 = vY2.x, h1 = h0 + vY2.y, h2 = h1 + vY2.z, h3 = h2 + vY2.w;
        float k0 = vY3.x, k1 = k0 + vY3.y, k2 = k1 + vY3.z, k3 = k2 + vY3.w;

        // eight simultaneous warp inclusive scans of lane sums
        float sA = a3, sB = b3, sD = d3, sE = e3;
        float sF = f3, sG = g3, sH = h3, sK = k3;
        #pragma unroll
        for (int o = 1; o < 32; o <<= 1) {
            float yA = __shfl_up_sync(0xFFFFFFFFu, sA, o);
            float yB = __shfl_up_sync(0xFFFFFFFFu, sB, o);
            float yD = __shfl_up_sync(0xFFFFFFFFu, sD, o);
            float yE = __shfl_up_sync(0xFFFFFFFFu, sE, o);
            float yF = __shfl_up_sync(0xFFFFFFFFu, sF, o);
            float yG = __shfl_up_sync(0xFFFFFFFFu, sG, o);
            float yH = __shfl_up_sync(0xFFFFFFFFu, sH, o);
            float yK = __shfl_up_sync(0xFFFFFFFFu, sK, o);
            if (lane >= o) {
                sA += yA; sB += yB; sD += yD; sE += yE;
                sF += yF; sG += yG; sH += yH; sK += yK;
            }
        }
        float TA = __shfl_sync(0xFFFFFFFFu, sA, 31);
        float TB = __shfl_sync(0xFFFFFFFFu, sB, 31);
        float TD = __shfl_sync(0xFFFFFFFFu, sD, 31);
        float TE = __shfl_sync(0xFFFFFFFFu, sE, 31);
        float TF = __shfl_sync(0xFFFFFFFFu, sF, 31);
        float TG = __shfl_sync(0xFFFFFFFFu, sG, 31);
        float TH = __shfl_sync(0xFFFFFFFFu, sH, 31);
        float TK = __shfl_sync(0xFFFFFFFFu, sK, 31);

        float baseA = offX + (sA - a3);
        float baseB = offX + TA + (sB - b3);
        float baseD = offX + TA + TB + (sD - d3);
        float baseE = offX + TA + TB + TD + (sE - e3);
        float baseF = offY + (sF - f3);
        float baseG = offY + TF + (sG - g3);
        float baseH = offY + TF + TG + (sH - h3);
        float baseK = offY + TF + TG + TH + (sK - k3);

        // cb chunk, shared by both rows (coalesced LDS.128)
        float4 c0 = cc[0], c1 = cc[32], c2 = cc[64], c3 = cc[96];

        acc0 += fabsf(baseA + a0 - c0.x);
        acc0 += fabsf(baseA + a1 - c0.y);
        acc0 += fabsf(baseA + a2 - c0.z);
        acc0 += fabsf(baseA + a3 - c0.w);
        acc1 += fabsf(baseB + b0 - c1.x);
        acc1 += fabsf(baseB + b1 - c1.y);
        acc1 += fabsf(baseB + b2 - c1.z);
        acc1 += fabsf(baseB + b3 - c1.w);
        acc2 += fabsf(baseD + d0 - c2.x);
        acc2 += fabsf(baseD + d1 - c2.y);
        acc2 += fabsf(baseD + d2 - c2.z);
        acc2 += fabsf(baseD + d3 - c2.w);
        acc3 += fabsf(baseE + e0 - c3.x);
        acc3 += fabsf(baseE + e1 - c3.y);
        acc3 += fabsf(baseE + e2 - c3.z);

        acc0 += fabsf(baseF + f0 - c0.x);
        acc0 += fabsf(baseF + f1 - c0.y);
        acc0 += fabsf(baseF + f2 - c0.z);
        acc0 += fabsf(baseF + f3 - c0.w);
        acc1 += fabsf(baseG + g0 - c1.x);
        acc1 += fabsf(baseG + g1 - c1.y);
        acc1 += fabsf(baseG + g2 - c1.z);
        acc1 += fabsf(baseG + g3 - c1.w);
        acc2 += fabsf(baseH + h0 - c2.x);
        acc2 += fabsf(baseH + h1 - c2.y);
        acc2 += fabsf(baseH + h2 - c2.z);
        acc2 += fabsf(baseH + h3 - c2.w);
        acc3 += fabsf(baseK + k0 - c3.x);
        acc3 += fabsf(baseK + k1 - c3.y);
        acc3 += fabsf(baseK + k2 - c3.z);

        if (!(c == 15 && lane == 31)) {          // exclude element N-1 (both rows)
            acc3 += fabsf(baseE + e3 - c3.w);
            acc3 += fabsf(baseK + k3 - c3.w);
        }

        offX = offX + TA + TB + TD + TE;
        offY = offY + TF + TG + TH + TK;

        vX0 = nX0; vX1 = nX1; vX2 = nX2; vX3 = nX3;
        vY0 = nY0; vY1 = nY1; vY2 = nY2; vY3 = nY3;
        pX += 128; pY += 128; cc += 128;
    }

    float acc = (acc0 + acc1) + (acc2 + acc3);

    // warp reduction + one atomic per warp
    #pragma unroll
    for (int o = 16; o > 0; o >>= 1)
        acc += __shfl_down_sync(0xFFFFFFFFu, acc, o);
    if (lane == 0)
        atomicAdd(out, acc);
}

// ---------------------------------------------------------------------------
extern "C" void kernel_launch(void* const* d_in, const int* in_sizes, int n_in,
                              void* d_out, int out_size)
{
    const float* x    = (const float*)d_in[0];   // [D, N] f32
    const float* bary = (const float*)d_in[1];   // [N] f32
    float* out = (float*)d_out;

    const int N = in_sizes[1];
    const int D = in_sizes[0] / N;
    (void)n_in; (void)out_size; (void)N;

    // out[0] = 0 via tiny D2D copy (stream-ordered before the kernel's atomics)
    void* zp = nullptr;
    cudaGetSymbolAddress(&zp, g_zero);
    cudaMemcpyAsync(out, zp, sizeof(float), cudaMemcpyDeviceToDevice, 0);

    row_w1_kernel<<<GBLOCKS, THREADS>>>(x, bary, out, D);
}